// round 15
// baseline (speedup 1.0000x reference)
#include <cuda_runtime.h>
#include <cuda_fp16.h>
#include <cstdint>

#define NB 4
#define NS 2048
#define NE 128
#define NH 16
#define ND 8
#define NBH (NB * NH)
#define KH 1024            // keys per CTA (half of NS)

// Staged head data (written by qgen, read by attn)
__device__ uint32_t g_kh[NBH * NS * 4];     // 2 MB fp16x2 CLS-scaled q/k
__device__ uint32_t g_vp[NBH * (NS/2) * 8]; // 2 MB pair-packed v*mask
__device__ float    g_num[2][NB * NS * NE]; // 8 MB partial numerators
__device__ float    g_den[2][NB * NS * NH]; // 1 MB partial denominators

__device__ __forceinline__ uint32_t ex2h2(uint32_t x) {
    uint32_t r; asm("ex2.approx.f16x2 %0,%1;" : "=r"(r) : "r"(x)); return r;
}
__device__ __forceinline__ uint32_t cvt_f16x2(float hi, float lo) {
    uint32_t r; asm("cvt.rn.f16x2.f32 %0,%1,%2;" : "=r"(r) : "f"(hi), "f"(lo)); return r;
}
// score MMA: m16n8k8, fp16 accumulate -> D already packed f16x2
__device__ __forceinline__ void mma16808h(uint32_t& dlo, uint32_t& dhi,
                                          uint32_t a0, uint32_t a1, uint32_t b0) {
    asm volatile("mma.sync.aligned.m16n8k8.row.col.f16.f16.f16.f16 "
                 "{%0,%1},{%2,%3},{%4},{%5,%5};"
                 : "=r"(dlo), "=r"(dhi)
                 : "r"(a0), "r"(a1), "r"(b0), "r"(0u));
}
__device__ __forceinline__ void mma16816(float c[4],
                                         uint32_t a0, uint32_t a1, uint32_t a2, uint32_t a3,
                                         uint32_t b0, uint32_t b1) {
    asm volatile("mma.sync.aligned.m16n8k16.row.col.f32.f16.f16.f32 "
                 "{%0,%1,%2,%3},{%4,%5,%6,%7},{%8,%9},{%0,%1,%2,%3};"
                 : "+f"(c[0]), "+f"(c[1]), "+f"(c[2]), "+f"(c[3])
                 : "r"(a0), "r"(a1), "r"(a2), "r"(a3), "r"(b0), "r"(b1));
}

// ---------------------------------------------------------------------------
// Kernel A: q = cumprod(cos(x+theta)); emit sqrtCL-scaled fp16 pairs
// (score operands) + mask-folded pair-packed V.  (unchanged from R13)
// ---------------------------------------------------------------------------
__global__ void __launch_bounds__(128) qgen_kernel(const float* __restrict__ x,
                                                   const float* __restrict__ theta,
                                                   const int* __restrict__ mask) {
    int r = blockIdx.x * blockDim.x + threadIdx.x;   // r = bh*NS + s
    if (r >= NBH * NS) return;
    int s  = r & (NS - 1);
    int bh = r >> 11;
    int h  = bh & (NH - 1);
    int b  = bh >> 4;

    const float4* xp = (const float4*)(x + ((size_t)(b * NS + s) * NE + h * ND));
    float4 x0 = xp[0], x1 = xp[1];

    float v[8];
    float p;
    p  = cosf(x0.x + theta[0]);  v[0] = p;
    p *= cosf(x0.y + theta[1]);  v[1] = p;
    p *= cosf(x0.z + theta[2]);  v[2] = p;
    p *= cosf(x0.w + theta[3]);  v[3] = p;
    p *= cosf(x1.x + theta[4]);  v[4] = p;
    p *= cosf(x1.y + theta[5]);  v[5] = p;
    p *= cosf(x1.z + theta[6]);  v[6] = p;
    p *= cosf(x1.w + theta[7]);  v[7] = p;

    const float CLS = 0.71421430302f;   // sqrt(log2(e)/sqrt(8))
    uint32_t hw[4];
#pragma unroll
    for (int j = 0; j < 4; ++j) {
        __half h0 = __float2half_rn(v[2 * j] * CLS);
        __half h1 = __float2half_rn(v[2 * j + 1] * CLS);
        hw[j] = (uint32_t)__half_as_ushort(h0) | ((uint32_t)__half_as_ushort(h1) << 16);
    }
    ((uint4*)g_kh)[r] = make_uint4(hw[0], hw[1], hw[2], hw[3]);

    float m = (float)mask[b * NS + s];
    uint16_t* vp16 = (uint16_t*)g_vp;
    size_t base = (((size_t)bh * (NS / 2) + (s >> 1)) * 8) * 2 + (s & 1);
#pragma unroll
    for (int n = 0; n < 8; ++n)
        vp16[base + 2 * n] = __half_as_ushort(__float2half_rn(v[n] * m));
}

// ---------------------------------------------------------------------------
// Kernel B: HMMA flash attention, key-split (byte-identical to R13).
// ---------------------------------------------------------------------------
__global__ void __launch_bounds__(256) attn_kernel(const int* __restrict__ mask) {
    extern __shared__ char smem[];
    uint32_t* sKh = (uint32_t*)smem;                    // 16 KB
    uint32_t* sVp = sKh + KH * 4;                       // 16 KB
    uint32_t* sVm = sVp + KH * 4;                       //  2 KB

    int tid = threadIdx.x;
    int bh = blockIdx.x;
    int kh = blockIdx.z;
    int b  = bh >> 4;
    int h  = bh & (NH - 1);

    {
        const uint4* gh = (const uint4*)(g_kh + ((size_t)bh * NS + kh * KH) * 4);
        const uint4* gv = (const uint4*)(g_vp + ((size_t)bh * (NS / 2) + kh * (KH / 2)) * 8);
        for (int s = tid; s < KH; s += 256) {
            uint4 k = gh[s];
            uint32_t* d = sKh + ((s >> 4) * 64 + (s & 7) * 8 + ((s >> 3) & 1));
            d[0] = k.x; d[2] = k.y; d[4] = k.z; d[6] = k.w;
        }
        for (int i = tid; i < KH; i += 256) {
            uint4 v = gv[i];
            int p = i >> 1;
            uint32_t* d = sVp + ((p >> 3) * 64 + (i & 1) * 32 + (p & 3) * 2 + ((p >> 2) & 1));
            d[0] = v.x; d[8] = v.y; d[16] = v.z; d[24] = v.w;
        }
        const int* mrow = mask + b * NS + kh * KH;
        for (int i = tid; i < KH / 2; i += 256) {
            __half m0 = __float2half_rn((float)mrow[2 * i]);
            __half m1 = __float2half_rn((float)mrow[2 * i + 1]);
            uint32_t pk = (uint32_t)__half_as_ushort(m0) | ((uint32_t)__half_as_ushort(m1) << 16);
            sVm[(i >> 3) * 8 + (i & 3) * 2 + ((i >> 2) & 1)] = pk;
        }
    }
    __syncthreads();

    int warp = tid >> 5, lane = tid & 31;
    int r0 = lane >> 2, cp = lane & 3;
    int qw = blockIdx.y * 128 + warp * 16;

    const uint32_t* gkh = g_kh + (size_t)bh * NS * 4;
    uint32_t A0 = gkh[(qw + r0) * 4 + cp];
    uint32_t A1 = gkh[(qw + r0 + 8) * 4 + cp];

    float o[4]  = {0.f, 0.f, 0.f, 0.f};
    float o2[4] = {0.f, 0.f, 0.f, 0.f};

    const int off  = r0 * 8 + cp * 2;
    const int offm = cp * 2;

#pragma unroll 4
    for (int it = 0; it < KH / 16; ++it) {
        uint2 kk = *(const uint2*)(sKh + it * 64 + off);
        uint2 vv = *(const uint2*)(sVp + it * 64 + off);
        uint2 mm = *(const uint2*)(sVm + it * 8 + offm);

        uint32_t d0l, d0h, d1l, d1h;
        mma16808h(d0l, d0h, A0, A1, kk.x);
        mma16808h(d1l, d1h, A0, A1, kk.y);

        uint32_t pe0 = ex2h2(d0l);
        uint32_t pe1 = ex2h2(d0h);
        uint32_t po0 = ex2h2(d1l);
        uint32_t po1 = ex2h2(d1h);

        mma16816(o,  pe0, pe1, po0, po1, vv.x, vv.y);
        mma16816(o2, pe0, pe1, po0, po1, mm.x, mm.y);
    }

    float* nump = g_num[kh];
    size_t col = (size_t)h * ND + 2 * cp;
    float2* out0 = (float2*)(nump + ((size_t)(b * NS + qw + r0) * NE + col));
    float2* out1 = (float2*)(nump + ((size_t)(b * NS + qw + r0 + 8) * NE + col));
    *out0 = make_float2(o[0], o[1]);
    *out1 = make_float2(o[2], o[3]);
    if (cp == 0) {
        g_den[kh][(size_t)(b * NS + qw + r0) * NH + h]     = o2[0];
        g_den[kh][(size_t)(b * NS + qw + r0 + 8) * NH + h] = o2[2];
    }
}

// ---------------------------------------------------------------------------
// Kernel C (v4): TENSOR-CORE fused combine + output GEMM.
// CTA = 64 rows (grid 128), 128 threads (4 warps x 16-row m16 tiles).
// Stage: inv (4KB), w fp16 B-frags interleaved (32KB),
//        attn = (n0+n1)*inv as hi/lo fp16 A-frags (2x16KB).
// Compute: per warp 8 k-steps x 16 n-tiles x 2 HMMA (A_hi*B + A_lo*B), f32 C.
// ---------------------------------------------------------------------------
__global__ void __launch_bounds__(128) out_kernel(const float* __restrict__ w,
                                                  float* __restrict__ out) {
    extern __shared__ char smem4[];
    uint2* sBf  = (uint2*)smem4;                       // 4096 * 8B  = 32 KB
    uint4* sAh  = (uint4*)(smem4 + 32768);             // 1024 * 16B = 16 KB
    uint4* sAl  = (uint4*)(smem4 + 49152);             // 1024 * 16B = 16 KB
    float* sInv = (float*)(smem4 + 65536);             // 1024 * 4B  =  4 KB

    int tid = threadIdx.x;
    int R0  = blockIdx.x * 64;                         // first global row

    // ---- phase 1: inverse denominators + B (weight) fragments ----
    for (int i = tid; i < 1024; i += 128) {            // i = lrow*16 + h
        int r = R0 + (i >> 4);
        float den = g_den[0][(size_t)r * NH + (i & 15)] +
                    g_den[1][(size_t)r * NH + (i & 15)];
        sInv[i] = __fdividef(1.0f, fmaxf(den, 1e-30f));
    }
    for (int slot = tid; slot < 4096; slot += 128) {   // (s,j,lane) B frags
        int lane = slot & 31;
        int j    = (slot >> 5) & 15;
        int s    = slot >> 9;
        int r0   = lane >> 2, cp = lane & 3;
        int e    = j * 8 + r0;
        int f0   = s * 16 + cp * 2;
        float2 w0 = *(const float2*)(w + (size_t)e * NE + f0);
        float2 w1 = *(const float2*)(w + (size_t)e * NE + f0 + 8);
        sBf[slot] = make_uint2(cvt_f16x2(w0.y, w0.x), cvt_f16x2(w1.y, w1.x));
    }
    __syncthreads();

    // ---- phase 2: A fragments (combine + scale + hi/lo fp16 split) ----
    for (int slot = tid; slot < 1024; slot += 128) {   // (w_,s,lane)
        int lane = slot & 31;
        int s    = (slot >> 5) & 7;
        int w_   = slot >> 8;
        int r0   = lane >> 2, cp = lane & 3;
        int lrow = w_ * 16 + r0;                       // local row, +8 for upper
        int row  = R0 + lrow;
        int f0   = s * 16 + cp * 2;

        float i0a = sInv[lrow * 16 + 2 * s];
        float i1a = sInv[lrow * 16 + 2 * s + 1];
        float i0b = sInv[(lrow + 8) * 16 + 2 * s];
        float i1b = sInv[(lrow + 8) * 16 + 2 * s + 1];

        const float* n0 = g_num[0];
        const float* n1 = g_num[1];
        float2 pa = *(const float2*)(n0 + (size_t)row * NE + f0);
        float2 qa = *(const float2*)(n1 + (size_t)row * NE + f0);
        float2 pb = *(const float2*)(n0 + (size_t)(row + 8) * NE + f0);
        float2 qb = *(const float2*)(n1 + (size_t)(row + 8) * NE + f0);
        float2 pc = *(const float2*)(n0 + (size_t)row * NE + f0 + 8);
        float2 qc = *(const float2*)(n1 + (size_t)row * NE + f0 + 8);
        float2 pd = *(const float2*)(n0 + (size_t)(row + 8) * NE + f0 + 8);
        float2 qd = *(const float2*)(n1 + (size_t)(row + 8) * NE + f0 + 8);

        float v0 = (pa.x + qa.x) * i0a, v1 = (pa.y + qa.y) * i0a;   // row, f0
        float v2 = (pb.x + qb.x) * i0b, v3 = (pb.y + qb.y) * i0b;   // row+8, f0
        float v4 = (pc.x + qc.x) * i1a, v5 = (pc.y + qc.y) * i1a;   // row, f0+8
        float v6 = (pd.x + qd.x) * i1b, v7 = (pd.y + qd.y) * i1b;   // row+8, f0+8

        // hi/lo fp16 split (a = hi + lo exactly to fp32 rounding)
        float h0 = __half2float(__float2half_rn(v0));
        float h1 = __half2float(__float2half_rn(v1));
        float h2 = __half2float(__float2half_rn(v2));
        float h3 = __half2float(__float2half_rn(v3));
        float h4 = __half2float(__float2half_rn(v4));
        float h5 = __half2float(__float2half_rn(v5));
        float h6 = __half2float(__float2half_rn(v6));
        float h7 = __half2float(__float2half_rn(v7));

        sAh[slot] = make_uint4(cvt_f16x2(h1, h0), cvt_f16x2(h3, h2),
                               cvt_f16x2(h5, h4), cvt_f16x2(h7, h6));
        sAl[slot] = make_uint4(cvt_f16x2(v1 - h1, v0 - h0),
                               cvt_f16x2(v3 - h3, v2 - h2),
                               cvt_f16x2(v5 - h5, v4 - h4),
                               cvt_f16x2(v7 - h7, v6 - h6));
    }
    __syncthreads();

    // ---- phase 3: tensor-core GEMM ----
    int w_  = tid >> 5;
    int lane = tid & 31;
    int r0 = lane >> 2, cp = lane & 3;

    float c[16][4];
#pragma unroll
    for (int j = 0; j < 16; ++j) {
        c[j][0] = 0.f; c[j][1] = 0.f; c[j][2] = 0.f; c[j][3] = 0.f;
    }

#pragma unroll 1
    for (int s = 0; s < 8; ++s) {
        uint4 Ah = sAh[(w_ * 8 + s) * 32 + lane];
        uint4 Al = sAl[(w_ * 8 + s) * 32 + lane];
#pragma unroll
        for (int j = 0; j < 16; ++j) {
            uint2 B = sBf[(s * 16 + j) * 32 + lane];
            mma16816(c[j], Ah.x, Ah.y, Ah.z, Ah.w, B.x, B.y);
            mma16816(c[j], Al.x, Al.y, Al.z, Al.w, B.x, B.y);
        }
    }

    // ---- epilogue: c[j] -> out ----
    int rowA = R0 + w_ * 16 + r0;
#pragma unroll
    for (int j = 0; j < 16; ++j) {
        int e = j * 8 + 2 * cp;
        *(float2*)(out + (size_t)rowA * NE + e)       = make_float2(c[j][0], c[j][1]);
        *(float2*)(out + (size_t)(rowA + 8) * NE + e) = make_float2(c[j][2], c[j][3]);
    }
}

// ---------------------------------------------------------------------------
extern "C" void kernel_launch(void* const* d_in, const int* in_sizes, int n_in,
                              void* d_out, int out_size) {
    const float* x     = (const float*)d_in[0];
    const float* theta = (const float*)d_in[1];
    const float* w     = (const float*)d_in[2];
    const int*   mask  = (const int*)d_in[3];
    float*       out   = (float*)d_out;

    qgen_kernel<<<(NBH * NS) / 128, 128>>>(x, theta, mask);

    int smB = KH * 4 * 4 * 2 + (KH / 2) * 4;   // 34816 B
    cudaFuncSetAttribute(attn_kernel, cudaFuncAttributeMaxDynamicSharedMemorySize, smB);
    attn_kernel<<<dim3(NBH, NS / 128, 2), 256, smB>>>(mask);

    int smC = 32768 + 16384 + 16384 + 4096;    // 69632 B
    cudaFuncSetAttribute(out_kernel, cudaFuncAttributeMaxDynamicSharedMemorySize, smC);
    out_kernel<<<(NB * NS) / 64, 128, smC>>>(w, out);
}

// round 16
// speedup vs baseline: 1.1213x; 1.1213x over previous
#include <cuda_runtime.h>
#include <cuda_fp16.h>
#include <cstdint>

#define NB 4
#define NS 2048
#define NE 128
#define NH 16
#define ND 8
#define NBH (NB * NH)
#define KH 1024            // keys per CTA (half of NS)

// Staged head data (written by qgen, read by attn)
__device__ uint32_t g_kh[NBH * NS * 4];     // 2 MB fp16x2 CLS-scaled q/k
__device__ uint32_t g_vp[NBH * (NS/2) * 8]; // 2 MB pair-packed v*mask
__device__ float    g_num[2][NB * NS * NE]; // 8 MB partial numerators
__device__ float    g_den[2][NB * NS * NH]; // 1 MB partial denominators

__device__ __forceinline__ uint32_t ex2h2(uint32_t x) {
    uint32_t r; asm("ex2.approx.f16x2 %0,%1;" : "=r"(r) : "r"(x)); return r;
}
__device__ __forceinline__ uint32_t hadd2(uint32_t a, uint32_t b) {
    uint32_t r; asm("add.rn.f16x2 %0,%1,%2;" : "=r"(r) : "r"(a), "r"(b)); return r;
}
// score MMA: m16n8k8, fp16 accumulate, C = per-column mask bias (0 / -inf)
__device__ __forceinline__ void mma16808h(uint32_t& dlo, uint32_t& dhi,
                                          uint32_t a0, uint32_t a1, uint32_t b0,
                                          uint32_t cc) {
    asm volatile("mma.sync.aligned.m16n8k8.row.col.f16.f16.f16.f16 "
                 "{%0,%1},{%2,%3},{%4},{%5,%5};"
                 : "=r"(dlo), "=r"(dhi)
                 : "r"(a0), "r"(a1), "r"(b0), "r"(cc));
}
__device__ __forceinline__ void mma16816(float c[4],
                                         uint32_t a0, uint32_t a1, uint32_t a2, uint32_t a3,
                                         uint32_t b0, uint32_t b1) {
    asm volatile("mma.sync.aligned.m16n8k16.row.col.f32.f16.f16.f32 "
                 "{%0,%1,%2,%3},{%4,%5,%6,%7},{%8,%9},{%0,%1,%2,%3};"
                 : "+f"(c[0]), "+f"(c[1]), "+f"(c[2]), "+f"(c[3])
                 : "r"(a0), "r"(a1), "r"(a2), "r"(a3), "r"(b0), "r"(b1));
}

// ---------------------------------------------------------------------------
// Kernel A: q = cumprod(cos(x+theta)); emit sqrtCL-scaled fp16 pairs
// (score operands) + mask-folded pair-packed V.  (unchanged from R13)
// ---------------------------------------------------------------------------
__global__ void __launch_bounds__(128) qgen_kernel(const float* __restrict__ x,
                                                   const float* __restrict__ theta,
                                                   const int* __restrict__ mask) {
    int r = blockIdx.x * blockDim.x + threadIdx.x;   // r = bh*NS + s
    if (r >= NBH * NS) return;
    int s  = r & (NS - 1);
    int bh = r >> 11;
    int h  = bh & (NH - 1);
    int b  = bh >> 4;

    const float4* xp = (const float4*)(x + ((size_t)(b * NS + s) * NE + h * ND));
    float4 x0 = xp[0], x1 = xp[1];

    float v[8];
    float p;
    p  = cosf(x0.x + theta[0]);  v[0] = p;
    p *= cosf(x0.y + theta[1]);  v[1] = p;
    p *= cosf(x0.z + theta[2]);  v[2] = p;
    p *= cosf(x0.w + theta[3]);  v[3] = p;
    p *= cosf(x1.x + theta[4]);  v[4] = p;
    p *= cosf(x1.y + theta[5]);  v[5] = p;
    p *= cosf(x1.z + theta[6]);  v[6] = p;
    p *= cosf(x1.w + theta[7]);  v[7] = p;

    const float CLS = 0.71421430302f;   // sqrt(log2(e)/sqrt(8))
    uint32_t hw[4];
#pragma unroll
    for (int j = 0; j < 4; ++j) {
        __half h0 = __float2half_rn(v[2 * j] * CLS);
        __half h1 = __float2half_rn(v[2 * j + 1] * CLS);
        hw[j] = (uint32_t)__half_as_ushort(h0) | ((uint32_t)__half_as_ushort(h1) << 16);
    }
    ((uint4*)g_kh)[r] = make_uint4(hw[0], hw[1], hw[2], hw[3]);

    float m = (float)mask[b * NS + s];
    uint16_t* vp16 = (uint16_t*)g_vp;
    size_t base = (((size_t)bh * (NS / 2) + (s >> 1)) * 8) * 2 + (s & 1);
#pragma unroll
    for (int n = 0; n < 8; ++n)
        vp16[base + 2 * n] = __half_as_ushort(__float2half_rn(v[n] * m));
}

// ---------------------------------------------------------------------------
// Kernel B: HMMA flash attention, key-split. 3 HMMAs per 16q x 16k iter:
// 2 score MMAs (mask bias folded into the C operand -> masked e == 0) and
// 1 PV MMA. den computed on the (idle) FMA pipe: HADD2 pair-sum + f32 adds.
// ---------------------------------------------------------------------------
__global__ void __launch_bounds__(256) attn_kernel(const int* __restrict__ mask) {
    extern __shared__ char smem[];
    uint32_t* sKh = (uint32_t*)smem;                    // 16 KB
    uint32_t* sVp = sKh + KH * 4;                       // 16 KB
    uint32_t* sVm = sVp + KH * 4;                       //  2 KB fp16x2 bias pairs

    int tid = threadIdx.x;
    int bh = blockIdx.x;
    int kh = blockIdx.z;
    int b  = bh >> 4;
    int h  = bh & (NH - 1);

    {
        const uint4* gh = (const uint4*)(g_kh + ((size_t)bh * NS + kh * KH) * 4);
        const uint4* gv = (const uint4*)(g_vp + ((size_t)bh * (NS / 2) + kh * (KH / 2)) * 8);
        for (int s = tid; s < KH; s += 256) {
            uint4 k = gh[s];
            uint32_t* d = sKh + ((s >> 4) * 64 + (s & 7) * 8 + ((s >> 3) & 1));
            d[0] = k.x; d[2] = k.y; d[4] = k.z; d[6] = k.w;
        }
        for (int i = tid; i < KH; i += 256) {
            uint4 v = gv[i];
            int p = i >> 1;
            uint32_t* d = sVp + ((p >> 3) * 64 + (i & 1) * 32 + (p & 3) * 2 + ((p >> 2) & 1));
            d[0] = v.x; d[8] = v.y; d[16] = v.z; d[24] = v.w;
        }
        // mask BIAS pairs: 0x0000 for kept keys, 0xFC00 (-inf) for masked
        const int* mrow = mask + b * NS + kh * KH;
        for (int i = tid; i < KH / 2; i += 256) {
            uint32_t b0 = mrow[2 * i]     ? 0u : 0xFC00u;
            uint32_t b1 = mrow[2 * i + 1] ? 0u : 0xFC00u;
            sVm[(i >> 3) * 8 + (i & 3) * 2 + ((i >> 2) & 1)] = b0 | (b1 << 16);
        }
    }
    __syncthreads();

    int warp = tid >> 5, lane = tid & 31;
    int r0 = lane >> 2, cp = lane & 3;
    int qw = blockIdx.y * 128 + warp * 16;

    const uint32_t* gkh = g_kh + (size_t)bh * NS * 4;
    uint32_t A0 = gkh[(qw + r0) * 4 + cp];
    uint32_t A1 = gkh[(qw + r0 + 8) * 4 + cp];

    float o[4] = {0.f, 0.f, 0.f, 0.f};      // PV accumulator
    float fd0 = 0.f, fd1 = 0.f;             // den (rows r0, r0+8)

    const int off  = r0 * 8 + cp * 2;
    const int offm = cp * 2;

#pragma unroll 4
    for (int it = 0; it < KH / 16; ++it) {
        uint2 kk = *(const uint2*)(sKh + it * 64 + off);
        uint2 vv = *(const uint2*)(sVp + it * 64 + off);
        uint2 mm = *(const uint2*)(sVm + it * 8 + offm);   // bias pairs

        uint32_t d0l, d0h, d1l, d1h;
        mma16808h(d0l, d0h, A0, A1, kk.x, mm.x);           // keys 0-7 (+bias)
        mma16808h(d1l, d1h, A0, A1, kk.y, mm.y);           // keys 8-15 (+bias)

        uint32_t pe0 = ex2h2(d0l);   // row r0,   keys 2cp..2cp+1   (masked->0)
        uint32_t pe1 = ex2h2(d0h);   // row r0+8
        uint32_t po0 = ex2h2(d1l);   // row r0,   keys 8+2cp
        uint32_t po1 = ex2h2(d1h);   // row r0+8

        mma16816(o, pe0, pe1, po0, po1, vv.x, vv.y);       // numerator

        // den on the FMA pipe: one fp16 pair-add, then exact f32 accumulation
        uint32_t sA = hadd2(pe0, po0);
        uint32_t sB = hadd2(pe1, po1);
        float2 fa = __half22float2(*(__half2*)&sA);
        float2 fb = __half22float2(*(__half2*)&sB);
        fd0 += fa.x + fa.y;
        fd1 += fb.x + fb.y;
    }

    // den: reduce across the quad (cp lanes hold disjoint key subsets)
    fd0 += __shfl_xor_sync(0xffffffffu, fd0, 1);
    fd0 += __shfl_xor_sync(0xffffffffu, fd0, 2);
    fd1 += __shfl_xor_sync(0xffffffffu, fd1, 1);
    fd1 += __shfl_xor_sync(0xffffffffu, fd1, 2);

    float* nump = g_num[kh];
    size_t col = (size_t)h * ND + 2 * cp;
    float2* out0 = (float2*)(nump + ((size_t)(b * NS + qw + r0) * NE + col));
    float2* out1 = (float2*)(nump + ((size_t)(b * NS + qw + r0 + 8) * NE + col));
    *out0 = make_float2(o[0], o[1]);
    *out1 = make_float2(o[2], o[3]);
    if (cp == 0) {
        g_den[kh][(size_t)(b * NS + qw + r0) * NH + h]     = fd0;
        g_den[kh][(size_t)(b * NS + qw + r0 + 8) * NH + h] = fd1;
    }
}

// ---------------------------------------------------------------------------
// Kernel C (v3): fused combine + output GEMM, bounded unroll (R13-identical).
// ---------------------------------------------------------------------------
__global__ void __launch_bounds__(256) out_kernel(const float* __restrict__ w,
                                                  float* __restrict__ out) {
    extern __shared__ float sW[];            // [128][132] + 256 invs
    float* sInv = sW + NE * 132;

    int tid = threadIdx.x;
    for (int i = tid; i < NE * NE; i += 256) {
        int e = i >> 7;
        int f = i & 127;
        sW[f * 132 + e] = w[i];
    }
    int rbase = blockIdx.x * 16;
    {
        int r = rbase + (tid >> 4);
        int h = tid & 15;
        float den = g_den[0][(size_t)r * NH + h] + g_den[1][(size_t)r * NH + h];
        sInv[tid] = __fdividef(1.0f, fmaxf(den, 1e-30f));
    }
    __syncthreads();

    int warp = tid >> 5;
    int lane = tid & 31;
    int rA = rbase + warp * 2;
    int rB = rA + 1;

    const float4* n0A = (const float4*)(g_num[0] + (size_t)rA * NE);
    const float4* n1A = (const float4*)(g_num[1] + (size_t)rA * NE);
    const float4* n0B = (const float4*)(g_num[0] + (size_t)rB * NE);
    const float4* n1B = (const float4*)(g_num[1] + (size_t)rB * NE);
    const float* invA = sInv + (warp * 2) * 16;
    const float* invB = invA + 16;

    float4 accA = make_float4(0.f, 0.f, 0.f, 0.f);
    float4 accB = make_float4(0.f, 0.f, 0.f, 0.f);

#pragma unroll 4
    for (int fi = 0; fi < 32; ++fi) {
        float4 a0 = n0A[fi], a1 = n1A[fi];
        float4 b0 = n0B[fi], b1 = n1B[fi];
        float iA = invA[fi >> 1];
        float iB = invB[fi >> 1];
        float axA = (a0.x + a1.x) * iA, ayA = (a0.y + a1.y) * iA;
        float azA = (a0.z + a1.z) * iA, awA = (a0.w + a1.w) * iA;
        float axB = (b0.x + b1.x) * iB, ayB = (b0.y + b1.y) * iB;
        float azB = (b0.z + b1.z) * iB, awB = (b0.w + b1.w) * iB;

        int f = fi * 4;
        float4 w0 = *(const float4*)&sW[(f + 0) * 132 + lane * 4];
        accA.x = fmaf(axA, w0.x, accA.x);  accB.x = fmaf(axB, w0.x, accB.x);
        accA.y = fmaf(axA, w0.y, accA.y);  accB.y = fmaf(axB, w0.y, accB.y);
        accA.z = fmaf(axA, w0.z, accA.z);  accB.z = fmaf(axB, w0.z, accB.z);
        accA.w = fmaf(axA, w0.w, accA.w);  accB.w = fmaf(axB, w0.w, accB.w);
        float4 w1 = *(const float4*)&sW[(f + 1) * 132 + lane * 4];
        accA.x = fmaf(ayA, w1.x, accA.x);  accB.x = fmaf(ayB, w1.x, accB.x);
        accA.y = fmaf(ayA, w1.y, accA.y);  accB.y = fmaf(ayB, w1.y, accB.y);
        accA.z = fmaf(ayA, w1.z, accA.z);  accB.z = fmaf(ayB, w1.z, accB.z);
        accA.w = fmaf(ayA, w1.w, accA.w);  accB.w = fmaf(ayB, w1.w, accB.w);
        float4 w2 = *(const float4*)&sW[(f + 2) * 132 + lane * 4];
        accA.x = fmaf(azA, w2.x, accA.x);  accB.x = fmaf(azB, w2.x, accB.x);
        accA.y = fmaf(azA, w2.y, accA.y);  accB.y = fmaf(azB, w2.y, accB.y);
        accA.z = fmaf(azA, w2.z, accA.z);  accB.z = fmaf(azB, w2.z, accB.z);
        accA.w = fmaf(azA, w2.w, accA.w);  accB.w = fmaf(azB, w2.w, accB.w);
        float4 w3 = *(const float4*)&sW[(f + 3) * 132 + lane * 4];
        accA.x = fmaf(awA, w3.x, accA.x);  accB.x = fmaf(awB, w3.x, accB.x);
        accA.y = fmaf(awA, w3.y, accA.y);  accB.y = fmaf(awB, w3.y, accB.y);
        accA.z = fmaf(awA, w3.z, accA.z);  accB.z = fmaf(awB, w3.z, accB.z);
        accA.w = fmaf(awA, w3.w, accA.w);  accB.w = fmaf(awB, w3.w, accB.w);
    }

    *(float4*)(out + (size_t)rA * NE + lane * 4) = accA;
    *(float4*)(out + (size_t)rB * NE + lane * 4) = accB;
}

// ---------------------------------------------------------------------------
extern "C" void kernel_launch(void* const* d_in, const int* in_sizes, int n_in,
                              void* d_out, int out_size) {
    const float* x     = (const float*)d_in[0];
    const float* theta = (const float*)d_in[1];
    const float* w     = (const float*)d_in[2];
    const int*   mask  = (const int*)d_in[3];
    float*       out   = (float*)d_out;

    qgen_kernel<<<(NBH * NS) / 128, 128>>>(x, theta, mask);

    int smB = KH * 4 * 4 * 2 + (KH / 2) * 4;   // 34816 B
    cudaFuncSetAttribute(attn_kernel, cudaFuncAttributeMaxDynamicSharedMemorySize, smB);
    attn_kernel<<<dim3(NBH, NS / 128, 2), 256, smB>>>(mask);

    int smC = NE * 132 * 4 + 256 * 4;          // 68608 B
    cudaFuncSetAttribute(out_kernel, cudaFuncAttributeMaxDynamicSharedMemorySize, smC);
    out_kernel<<<(NB * NS) / 16, 256, smC>>>(w, out);
}

// round 17
// speedup vs baseline: 1.3954x; 1.2445x over previous
#include <cuda_runtime.h>
#include <cuda_fp16.h>
#include <cstdint>

#define NB 4
#define NS 2048
#define NE 128
#define NH 16
#define ND 8
#define NBH (NB * NH)
#define KH 1024            // keys per CTA (half of NS)

// Staged head data (written by qgen, read by attn)
__device__ uint32_t g_kh[NBH * NS * 4];     // 2 MB fp16x2 CLS-scaled q/k
__device__ uint32_t g_vp[NBH * (NS/2) * 8]; // 2 MB pair-packed v*mask
__device__ float    g_num[2][NB * NS * NE]; // 8 MB partial numerators
__device__ float    g_den[2][NB * NS * NH]; // 1 MB partial denominators

__device__ __forceinline__ uint32_t ex2h2(uint32_t x) {
    uint32_t r; asm("ex2.approx.f16x2 %0,%1;" : "=r"(r) : "r"(x)); return r;
}
__device__ __forceinline__ uint32_t hadd2(uint32_t a, uint32_t b) {
    uint32_t r; asm("add.rn.f16x2 %0,%1,%2;" : "=r"(r) : "r"(a), "r"(b)); return r;
}
__device__ __forceinline__ uint32_t cvt_f16x2(float hi, float lo) {
    uint32_t r; asm("cvt.rn.f16x2.f32 %0,%1,%2;" : "=r"(r) : "f"(hi), "f"(lo)); return r;
}
// score MMA: m16n8k8, fp16 accumulate, C = per-column mask bias (0 / -inf)
__device__ __forceinline__ void mma16808h(uint32_t& dlo, uint32_t& dhi,
                                          uint32_t a0, uint32_t a1, uint32_t b0,
                                          uint32_t cc) {
    asm volatile("mma.sync.aligned.m16n8k8.row.col.f16.f16.f16.f16 "
                 "{%0,%1},{%2,%3},{%4},{%5,%5};"
                 : "=r"(dlo), "=r"(dhi)
                 : "r"(a0), "r"(a1), "r"(b0), "r"(cc));
}
__device__ __forceinline__ void mma16816(float c[4],
                                         uint32_t a0, uint32_t a1, uint32_t a2, uint32_t a3,
                                         uint32_t b0, uint32_t b1) {
    asm volatile("mma.sync.aligned.m16n8k16.row.col.f32.f16.f16.f32 "
                 "{%0,%1,%2,%3},{%4,%5,%6,%7},{%8,%9},{%0,%1,%2,%3};"
                 : "+f"(c[0]), "+f"(c[1]), "+f"(c[2]), "+f"(c[3])
                 : "r"(a0), "r"(a1), "r"(a2), "r"(a3), "r"(b0), "r"(b1));
}

// ---------------------------------------------------------------------------
// Kernel A: q = cumprod(cos(x+theta)); emit sqrtCL-scaled fp16 pairs
// (score operands) + mask-folded pair-packed V.  (unchanged from R16)
// ---------------------------------------------------------------------------
__global__ void __launch_bounds__(128) qgen_kernel(const float* __restrict__ x,
                                                   const float* __restrict__ theta,
                                                   const int* __restrict__ mask) {
    int r = blockIdx.x * blockDim.x + threadIdx.x;   // r = bh*NS + s
    if (r >= NBH * NS) return;
    int s  = r & (NS - 1);
    int bh = r >> 11;
    int h  = bh & (NH - 1);
    int b  = bh >> 4;

    const float4* xp = (const float4*)(x + ((size_t)(b * NS + s) * NE + h * ND));
    float4 x0 = xp[0], x1 = xp[1];

    float v[8];
    float p;
    p  = cosf(x0.x + theta[0]);  v[0] = p;
    p *= cosf(x0.y + theta[1]);  v[1] = p;
    p *= cosf(x0.z + theta[2]);  v[2] = p;
    p *= cosf(x0.w + theta[3]);  v[3] = p;
    p *= cosf(x1.x + theta[4]);  v[4] = p;
    p *= cosf(x1.y + theta[5]);  v[5] = p;
    p *= cosf(x1.z + theta[6]);  v[6] = p;
    p *= cosf(x1.w + theta[7]);  v[7] = p;

    const float CLS = 0.71421430302f;   // sqrt(log2(e)/sqrt(8))
    uint32_t hw[4];
#pragma unroll
    for (int j = 0; j < 4; ++j) {
        __half h0 = __float2half_rn(v[2 * j] * CLS);
        __half h1 = __float2half_rn(v[2 * j + 1] * CLS);
        hw[j] = (uint32_t)__half_as_ushort(h0) | ((uint32_t)__half_as_ushort(h1) << 16);
    }
    ((uint4*)g_kh)[r] = make_uint4(hw[0], hw[1], hw[2], hw[3]);

    float m = (float)mask[b * NS + s];
    uint16_t* vp16 = (uint16_t*)g_vp;
    size_t base = (((size_t)bh * (NS / 2) + (s >> 1)) * 8) * 2 + (s & 1);
#pragma unroll
    for (int n = 0; n < 8; ++n)
        vp16[base + 2 * n] = __half_as_ushort(__float2half_rn(v[n] * m));
}

// ---------------------------------------------------------------------------
// Kernel B: HMMA flash attention, key-split, 3 HMMAs/iter (unchanged from R16)
// ---------------------------------------------------------------------------
__global__ void __launch_bounds__(256) attn_kernel(const int* __restrict__ mask) {
    extern __shared__ char smem[];
    uint32_t* sKh = (uint32_t*)smem;                    // 16 KB
    uint32_t* sVp = sKh + KH * 4;                       // 16 KB
    uint32_t* sVm = sVp + KH * 4;                       //  2 KB fp16x2 bias pairs

    int tid = threadIdx.x;
    int bh = blockIdx.x;
    int kh = blockIdx.z;
    int b  = bh >> 4;
    int h  = bh & (NH - 1);

    {
        const uint4* gh = (const uint4*)(g_kh + ((size_t)bh * NS + kh * KH) * 4);
        const uint4* gv = (const uint4*)(g_vp + ((size_t)bh * (NS / 2) + kh * (KH / 2)) * 8);
        for (int s = tid; s < KH; s += 256) {
            uint4 k = gh[s];
            uint32_t* d = sKh + ((s >> 4) * 64 + (s & 7) * 8 + ((s >> 3) & 1));
            d[0] = k.x; d[2] = k.y; d[4] = k.z; d[6] = k.w;
        }
        for (int i = tid; i < KH; i += 256) {
            uint4 v = gv[i];
            int p = i >> 1;
            uint32_t* d = sVp + ((p >> 3) * 64 + (i & 1) * 32 + (p & 3) * 2 + ((p >> 2) & 1));
            d[0] = v.x; d[8] = v.y; d[16] = v.z; d[24] = v.w;
        }
        const int* mrow = mask + b * NS + kh * KH;
        for (int i = tid; i < KH / 2; i += 256) {
            uint32_t b0 = mrow[2 * i]     ? 0u : 0xFC00u;
            uint32_t b1 = mrow[2 * i + 1] ? 0u : 0xFC00u;
            sVm[(i >> 3) * 8 + (i & 3) * 2 + ((i >> 2) & 1)] = b0 | (b1 << 16);
        }
    }
    __syncthreads();

    int warp = tid >> 5, lane = tid & 31;
    int r0 = lane >> 2, cp = lane & 3;
    int qw = blockIdx.y * 128 + warp * 16;

    const uint32_t* gkh = g_kh + (size_t)bh * NS * 4;
    uint32_t A0 = gkh[(qw + r0) * 4 + cp];
    uint32_t A1 = gkh[(qw + r0 + 8) * 4 + cp];

    float o[4] = {0.f, 0.f, 0.f, 0.f};
    float fd0 = 0.f, fd1 = 0.f;

    const int off  = r0 * 8 + cp * 2;
    const int offm = cp * 2;

#pragma unroll 4
    for (int it = 0; it < KH / 16; ++it) {
        uint2 kk = *(const uint2*)(sKh + it * 64 + off);
        uint2 vv = *(const uint2*)(sVp + it * 64 + off);
        uint2 mm = *(const uint2*)(sVm + it * 8 + offm);

        uint32_t d0l, d0h, d1l, d1h;
        mma16808h(d0l, d0h, A0, A1, kk.x, mm.x);
        mma16808h(d1l, d1h, A0, A1, kk.y, mm.y);

        uint32_t pe0 = ex2h2(d0l);
        uint32_t pe1 = ex2h2(d0h);
        uint32_t po0 = ex2h2(d1l);
        uint32_t po1 = ex2h2(d1h);

        mma16816(o, pe0, pe1, po0, po1, vv.x, vv.y);

        uint32_t sA = hadd2(pe0, po0);
        uint32_t sB = hadd2(pe1, po1);
        float2 fa = __half22float2(*(__half2*)&sA);
        float2 fb = __half22float2(*(__half2*)&sB);
        fd0 += fa.x + fa.y;
        fd1 += fb.x + fb.y;
    }

    fd0 += __shfl_xor_sync(0xffffffffu, fd0, 1);
    fd0 += __shfl_xor_sync(0xffffffffu, fd0, 2);
    fd1 += __shfl_xor_sync(0xffffffffu, fd1, 1);
    fd1 += __shfl_xor_sync(0xffffffffu, fd1, 2);

    float* nump = g_num[kh];
    size_t col = (size_t)h * ND + 2 * cp;
    float2* out0 = (float2*)(nump + ((size_t)(b * NS + qw + r0) * NE + col));
    float2* out1 = (float2*)(nump + ((size_t)(b * NS + qw + r0 + 8) * NE + col));
    *out0 = make_float2(o[0], o[1]);
    *out1 = make_float2(o[2], o[3]);
    if (cp == 0) {
        g_den[kh][(size_t)(b * NS + qw + r0) * NH + h]     = fd0;
        g_den[kh][(size_t)(b * NS + qw + r0 + 8) * NH + h] = fd1;
    }
}

// ---------------------------------------------------------------------------
// Kernel C (v5): tensor-core fused combine + output GEMM, high occupancy.
// 512 CTAs x 256 threads, 16 rows/CTA, 73.7 KB SMEM -> 3 CTAs/SM.
// A = (n0+n1)*inv split hi/lo fp16; W split hi/lo fp16.
// D = Ah*Wh + Al*Wh + Ah*Wl (fp32 acc) -> error ~1e-6 from the GEMM.
// Each warp: 2 n-tiles (16 cols) x 8 k-steps x 3 MMAs = 48 MMAs.
// ---------------------------------------------------------------------------
__global__ void __launch_bounds__(256) out_kernel(const float* __restrict__ w,
                                                  float* __restrict__ out) {
    extern __shared__ char sm5[];
    uint2* sBh  = (uint2*)sm5;                         // 4096*8  = 32 KB
    uint2* sBl  = (uint2*)(sm5 + 32768);               // 4096*8  = 32 KB
    uint4* sAh  = (uint4*)(sm5 + 65536);               // 256*16  =  4 KB
    uint4* sAl  = (uint4*)(sm5 + 69632);               // 256*16  =  4 KB
    float* sInv = (float*)(sm5 + 73728);               // 256*4   =  1 KB

    int tid = threadIdx.x;
    int R0  = blockIdx.x * 16;

    // ---- inverse denominators (coalesced) ----
    {
        int r = R0 + (tid >> 4);
        float den = g_den[0][(size_t)r * NH + (tid & 15)] +
                    g_den[1][(size_t)r * NH + (tid & 15)];
        sInv[tid] = __fdividef(1.0f, fmaxf(den, 1e-30f));
    }

    // ---- B fragments: w -> hi/lo fp16, frag-interleaved ----
    for (int slot = tid; slot < 4096; slot += 256) {
        int l  = slot & 31;
        int jj = (slot >> 5) & 15;
        int s  = slot >> 9;
        int rr = l >> 2, cc = l & 3;
        int e  = jj * 8 + rr;
        int f0 = s * 16 + cc * 2;
        float2 w0 = *(const float2*)(w + (size_t)e * NE + f0);
        float2 w1 = *(const float2*)(w + (size_t)e * NE + f0 + 8);
        float h0 = __half2float(__float2half_rn(w0.x));
        float h1 = __half2float(__float2half_rn(w0.y));
        float h2 = __half2float(__float2half_rn(w1.x));
        float h3 = __half2float(__float2half_rn(w1.y));
        sBh[slot] = make_uint2(cvt_f16x2(h1, h0), cvt_f16x2(h3, h2));
        sBl[slot] = make_uint2(cvt_f16x2(w0.y - h1, w0.x - h0),
                               cvt_f16x2(w1.y - h3, w1.x - h2));
    }
    __syncthreads();   // sInv ready before A staging reads it

    // ---- A fragments: (n0+n1)*inv, hi/lo split ----
    {
        int s  = tid >> 5;                 // k-step 0..7
        int l  = tid & 31;
        int rr = l >> 2, cc = l & 3;
        int lrow = rr;                     // local rows rr and rr+8
        int row  = R0 + lrow;
        int f0 = s * 16 + cc * 2;

        float i0a = sInv[lrow * 16 + 2 * s];
        float i1a = sInv[lrow * 16 + 2 * s + 1];
        float i0b = sInv[(lrow + 8) * 16 + 2 * s];
        float i1b = sInv[(lrow + 8) * 16 + 2 * s + 1];

        const float* n0 = g_num[0];
        const float* n1 = g_num[1];
        float2 pa = *(const float2*)(n0 + (size_t)row * NE + f0);
        float2 qa = *(const float2*)(n1 + (size_t)row * NE + f0);
        float2 pb = *(const float2*)(n0 + (size_t)(row + 8) * NE + f0);
        float2 qb = *(const float2*)(n1 + (size_t)(row + 8) * NE + f0);
        float2 pc = *(const float2*)(n0 + (size_t)row * NE + f0 + 8);
        float2 qc = *(const float2*)(n1 + (size_t)row * NE + f0 + 8);
        float2 pd = *(const float2*)(n0 + (size_t)(row + 8) * NE + f0 + 8);
        float2 qd = *(const float2*)(n1 + (size_t)(row + 8) * NE + f0 + 8);

        float v0 = (pa.x + qa.x) * i0a, v1 = (pa.y + qa.y) * i0a;
        float v2 = (pb.x + qb.x) * i0b, v3 = (pb.y + qb.y) * i0b;
        float v4 = (pc.x + qc.x) * i1a, v5 = (pc.y + qc.y) * i1a;
        float v6 = (pd.x + qd.x) * i1b, v7 = (pd.y + qd.y) * i1b;

        float h0 = __half2float(__float2half_rn(v0));
        float h1 = __half2float(__float2half_rn(v1));
        float h2 = __half2float(__float2half_rn(v2));
        float h3 = __half2float(__float2half_rn(v3));
        float h4 = __half2float(__float2half_rn(v4));
        float h5 = __half2float(__float2half_rn(v5));
        float h6 = __half2float(__float2half_rn(v6));
        float h7 = __half2float(__float2half_rn(v7));

        sAh[s * 32 + l] = make_uint4(cvt_f16x2(h1, h0), cvt_f16x2(h3, h2),
                                     cvt_f16x2(h5, h4), cvt_f16x2(h7, h6));
        sAl[s * 32 + l] = make_uint4(cvt_f16x2(v1 - h1, v0 - h0),
                                     cvt_f16x2(v3 - h3, v2 - h2),
                                     cvt_f16x2(v5 - h5, v4 - h4),
                                     cvt_f16x2(v7 - h7, v6 - h6));
    }
    __syncthreads();

    // ---- tensor GEMM: each warp -> 16 rows x 16 cols ----
    int w_   = tid >> 5;
    int lane = tid & 31;
    int r0 = lane >> 2, cp = lane & 3;

    float c0[4] = {0.f, 0.f, 0.f, 0.f};
    float c1[4] = {0.f, 0.f, 0.f, 0.f};

#pragma unroll
    for (int s = 0; s < 8; ++s) {
        uint4 Ah = sAh[s * 32 + lane];
        uint4 Al = sAl[s * 32 + lane];
        int base = s * 512 + (w_ * 2) * 32 + lane;
        uint2 Bh0 = sBh[base];
        uint2 Bl0 = sBl[base];
        uint2 Bh1 = sBh[base + 32];
        uint2 Bl1 = sBl[base + 32];
        mma16816(c0, Ah.x, Ah.y, Ah.z, Ah.w, Bh0.x, Bh0.y);
        mma16816(c0, Al.x, Al.y, Al.z, Al.w, Bh0.x, Bh0.y);
        mma16816(c0, Ah.x, Ah.y, Ah.z, Ah.w, Bl0.x, Bl0.y);
        mma16816(c1, Ah.x, Ah.y, Ah.z, Ah.w, Bh1.x, Bh1.y);
        mma16816(c1, Al.x, Al.y, Al.z, Al.w, Bh1.x, Bh1.y);
        mma16816(c1, Ah.x, Ah.y, Ah.z, Ah.w, Bl1.x, Bl1.y);
    }

    // ---- epilogue ----
    int rowA = R0 + r0;
    int e0 = (w_ * 2) * 8 + 2 * cp;
    int e1 = e0 + 8;
    *(float2*)(out + (size_t)rowA * NE + e0)       = make_float2(c0[0], c0[1]);
    *(float2*)(out + (size_t)(rowA + 8) * NE + e0) = make_float2(c0[2], c0[3]);
    *(float2*)(out + (size_t)rowA * NE + e1)       = make_float2(c1[0], c1[1]);
    *(float2*)(out + (size_t)(rowA + 8) * NE + e1) = make_float2(c1[2], c1[3]);
}

// ---------------------------------------------------------------------------
extern "C" void kernel_launch(void* const* d_in, const int* in_sizes, int n_in,
                              void* d_out, int out_size) {
    const float* x     = (const float*)d_in[0];
    const float* theta = (const float*)d_in[1];
    const float* w     = (const float*)d_in[2];
    const int*   mask  = (const int*)d_in[3];
    float*       out   = (float*)d_out;

    qgen_kernel<<<(NBH * NS) / 128, 128>>>(x, theta, mask);

    int smB = KH * 4 * 4 * 2 + (KH / 2) * 4;   // 34816 B
    cudaFuncSetAttribute(attn_kernel, cudaFuncAttributeMaxDynamicSharedMemorySize, smB);
    attn_kernel<<<dim3(NBH, NS / 128, 2), 256, smB>>>(mask);

    int smC = 32768 + 32768 + 4096 + 4096 + 1024;   // 74752 B
    cudaFuncSetAttribute(out_kernel, cudaFuncAttributeMaxDynamicSharedMemorySize, smC);
    out_kernel<<<(NB * NS) / 16, 256, smC>>>(w, out);
}